// round 7
// baseline (speedup 1.0000x reference)
#include <cuda_runtime.h>
#include <cuda_bf16.h>
#include <math.h>
#include <stdint.h>

// Problem constants
#define NB 8
#define NC 256
#define NHW 1024
#define NROW 8192              // NB*NHW
#define INV_T 10.0f            // 1/TEMPERATURE
#define POS_COUNT 8388608.0    // 8192*1024

// ---------------- device scratch (no allocation allowed) ----------------
__device__ __align__(256) __nv_bfloat16 g_Rn[NROW * NC];   // normalized rgb (bf16, for k_row)
__device__ __align__(256) uint8_t g_R8[NROW * NC];         // normalized rgb (e4m3, for gemm)
__device__ __align__(256) uint8_t g_X8[NROW * NC];         // normalized x   (e4m3, for gemm)
__device__ float  g_Xsum[8 * NC];           // per-class (j%8) column sums of normalized x
__device__ float  g_rowsum[NROW];           // sum_j exp(sim_ij)
__device__ double g_acc;                    // global loss accumulator
__device__ unsigned g_done;                 // k_row completion counter

__device__ __forceinline__ float ex2f(float x) {
    float r; asm("ex2.approx.f32 %0, %1;" : "=f"(r) : "f"(x)); return r;
}
__device__ __forceinline__ uint16_t cvt_e4m3x2(float hi, float lo) {
    uint16_t h;
    asm("cvt.rn.satfinite.e4m3x2.f32 %0, %1, %2;" : "=h"(h) : "f"(hi), "f"(lo));
    return h;
}

// ---------------- init ---------------------------------------------------
__global__ void k_init() {
    int idx = blockIdx.x * blockDim.x + threadIdx.x;
    if (idx < NROW) g_rowsum[idx] = 0.0f;
    if (idx < 8 * NC) g_Xsum[idx] = 0.0f;
    if (idx == 0) { g_acc = 0.0; g_done = 0u; }
}

// ---------------- normalize (B,C,H,W) -> rows of 256: bf16 + e4m3 -------
// grid 512: blocks [0,256) process rgb, [256,512) process x.
__global__ void __launch_bounds__(256) k_norm(const float* __restrict__ rgb,
                                              const float* __restrict__ x) {
    __shared__ float s[32][257];
    __shared__ float ps[8][32];
    __shared__ float invs[32];

    int tid = threadIdx.x;
    int isX = blockIdx.x >> 8;
    int bix = blockIdx.x & 255;
    int b   = bix >> 5;
    int p0  = (bix & 31) << 5;
    int pl  = tid & 31;
    int cg  = tid >> 5;

    const float* in = isX ? x : rgb;
    const float* base = in + (size_t)b * NC * NHW + p0;
    #pragma unroll
    for (int co = 0; co < 32; ++co) {
        int c = co * 8 + cg;
        s[pl][c] = base[(size_t)c * NHW + pl];
    }
    __syncthreads();

    float part = 0.0f;
    #pragma unroll
    for (int k = 0; k < 32; ++k) {
        float v = s[pl][cg * 32 + k];
        part = fmaf(v, v, part);
    }
    ps[cg][pl] = part;
    __syncthreads();

    if (tid < 32) {
        float ss = 0.0f;
        #pragma unroll
        for (int j = 0; j < 8; ++j) ss += ps[j][tid];
        invs[tid] = 1.0f / fmaxf(sqrtf(ss), 1e-12f);
    }
    __syncthreads();

    float xacc[8];
    #pragma unroll
    for (int m = 0; m < 8; ++m) xacc[m] = 0.0f;

    // normalize in place; write bf16 copy (rgb only needed by k_row, but cheap for both)
    #pragma unroll
    for (int rl = 0; rl < 32; ++rl) {
        float v = s[rl][tid] * invs[rl];
        s[rl][tid] = v;
        if (!isX) g_Rn[(size_t)(b * NHW + p0 + rl) * NC + tid] = __float2bfloat16(v);
        xacc[rl & 7] += v;
    }
    if (isX) {
        #pragma unroll
        for (int m = 0; m < 8; ++m)
            atomicAdd(&g_Xsum[m * NC + tid], xacc[m]);
    }
    __syncthreads();

    // pack e4m3: thread handles row = tid>>3, channels seg..seg+31
    {
        uint8_t* out8 = isX ? g_X8 : g_R8;
        int row = tid >> 3;
        int seg = (tid & 7) * 32;
        uint32_t wbuf[8];
        #pragma unroll
        for (int i = 0; i < 8; ++i) {
            uint16_t h0 = cvt_e4m3x2(s[row][seg + 4 * i + 1], s[row][seg + 4 * i + 0]);
            uint16_t h1 = cvt_e4m3x2(s[row][seg + 4 * i + 3], s[row][seg + 4 * i + 2]);
            wbuf[i] = (uint32_t)h0 | ((uint32_t)h1 << 16);
        }
        uint4* dst = (uint4*)(out8 + (size_t)(b * NHW + p0 + row) * NC + seg);
        dst[0] = make_uint4(wbuf[0], wbuf[1], wbuf[2], wbuf[3]);
        dst[1] = make_uint4(wbuf[4], wbuf[5], wbuf[6], wbuf[7]);
    }
}

// ---------------- fp8 MMA helper -----------------------------------------
__device__ __forceinline__ void mma_e4m3(float c[4], const uint32_t a[4],
                                         uint32_t b0, uint32_t b1) {
    asm volatile(
        "mma.sync.aligned.m16n8k32.row.col.f32.e4m3.e4m3.f32 "
        "{%0,%1,%2,%3}, {%4,%5,%6,%7}, {%8,%9}, {%0,%1,%2,%3};"
        : "+f"(c[0]), "+f"(c[1]), "+f"(c[2]), "+f"(c[3])
        : "r"(a[0]), "r"(a[1]), "r"(a[2]), "r"(a[3]), "r"(b0), "r"(b1));
}
__device__ __forceinline__ uint32_t lds32(uint32_t addr) {
    uint32_t v; asm volatile("ld.shared.b32 %0, [%1];" : "=r"(v) : "r"(addr)); return v;
}

// B tile smem: 64 rows (x-cols) x 256 e4m3 bytes, row stride 272B (bank-safe)
#define BROW 272u
#define BUFW (64u * BROW)      // 17408 bytes per stage

// issue 64x256 e4m3 tile load (16KB) via cp.async
__device__ __forceinline__ void issue_load8(uint32_t dst_base,
                                            const uint8_t* src_base, int tid) {
    #pragma unroll
    for (int it = 0; it < 4; ++it) {
        int idx = tid + it * 256;
        int r = idx >> 4, ch = idx & 15;
        uint32_t dst = dst_base + (uint32_t)r * BROW + (uint32_t)ch * 16u;
        asm volatile("cp.async.cg.shared.global [%0], [%1], 16;"
                     :: "r"(dst), "l"(src_base + (size_t)r * 256 + ch * 16) : "memory");
    }
    asm volatile("cp.async.commit_group;" ::: "memory");
}

// ---------------- fused fp8 GEMM + exp row-sum ---------------------------
// 512 blocks: 64 row-blocks (128 rows) x 8 column slices (1024 cols).
// Per CTA: 16 B-tiles of 64 cols, 3-stage cp.async pipeline.
// 8 warps; warp owns 16 rows; A (fp8) register-resident for full K=256.
__global__ void __launch_bounds__(256, 2) k_gemm() {
    extern __shared__ uint32_t Xs[];   // 3 stages of 64*272 bytes

    int tid  = threadIdx.x;
    int w    = tid >> 5;
    int lane = tid & 31;
    int g    = lane >> 2;
    int tig  = lane & 3;

    int rowBlk = blockIdx.x & 63;
    int cslice = blockIdx.x >> 6;          // 0..7
    int r0     = rowBlk * 128;
    int cstart = cslice * 1024;

    int rg = r0 + w * 16 + g;
    const uint32_t* Ra = (const uint32_t*)(g_R8 + (size_t)rg * NC);
    const uint32_t* Rb = (const uint32_t*)(g_R8 + (size_t)(rg + 8) * NC);

    // A fragments (fp8) for full K=256: 8 k-chunks of 32
    uint32_t a[8][4];
    #pragma unroll
    for (int kc = 0; kc < 8; ++kc) {
        a[kc][0] = Ra[kc * 8 + tig];
        a[kc][1] = Rb[kc * 8 + tig];
        a[kc][2] = Ra[kc * 8 + 4 + tig];
        a[kc][3] = Rb[kc * 8 + 4 + tig];
    }

    uint32_t sbase = (uint32_t)__cvta_generic_to_shared(Xs);

    float rs0 = 0.0f, rs1 = 0.0f;
    const float S = 14.426950408889634f;   // log2(e)/0.1

    const uint8_t* xb = g_X8 + (size_t)cstart * NC;
    issue_load8(sbase,        xb,       tid);
    issue_load8(sbase + BUFW, xb + 64 * NC, tid);

    #pragma unroll 1
    for (int nt = 0; nt < 16; ++nt) {
        if (nt < 15) {
            asm volatile("cp.async.wait_group 1;" ::: "memory");
        } else {
            asm volatile("cp.async.wait_group 0;" ::: "memory");
        }
        __syncthreads();
        if (nt + 2 < 16)
            issue_load8(sbase + (uint32_t)((nt + 2) % 3) * BUFW,
                        xb + (size_t)(nt + 2) * 64 * NC, tid);

        uint32_t bbase = sbase + (uint32_t)(nt % 3) * BUFW;

        #pragma unroll
        for (int np = 0; np < 4; ++np) {
            float c0[4] = {0.f, 0.f, 0.f, 0.f};
            float c1[4] = {0.f, 0.f, 0.f, 0.f};
            // n rows for the two 8-col blocks: np*16 + (lane>>2) and +8
            uint32_t nb = bbase + (uint32_t)(np * 16 + g) * BROW + (uint32_t)tig * 4u;
            #pragma unroll
            for (int kc = 0; kc < 8; ++kc) {
                uint32_t b00 = lds32(nb + (uint32_t)kc * 32u);
                uint32_t b01 = lds32(nb + (uint32_t)kc * 32u + 16u);
                uint32_t b10 = lds32(nb + 8u * BROW + (uint32_t)kc * 32u);
                uint32_t b11 = lds32(nb + 8u * BROW + (uint32_t)kc * 32u + 16u);
                mma_e4m3(c0, a[kc], b00, b01);
                mma_e4m3(c1, a[kc], b10, b11);
            }
            rs0 += ex2f(c0[0] * S) + ex2f(c0[1] * S) + ex2f(c1[0] * S) + ex2f(c1[1] * S);
            rs1 += ex2f(c0[2] * S) + ex2f(c0[3] * S) + ex2f(c1[2] * S) + ex2f(c1[3] * S);
        }
    }

    rs0 += __shfl_xor_sync(0xffffffffu, rs0, 1);
    rs0 += __shfl_xor_sync(0xffffffffu, rs0, 2);
    rs1 += __shfl_xor_sync(0xffffffffu, rs1, 1);
    rs1 += __shfl_xor_sync(0xffffffffu, rs1, 2);
    if (tig == 0) {
        atomicAdd(&g_rowsum[rg], rs0);
        atomicAdd(&g_rowsum[rg + 8], rs1);
    }
}

// ---------------- per-row: 1024*log(rowsum) - posdot/T ------------------
// grid 64, block 256: warp handles 16 rows (4 batches of 4 for MLP);
// Xsum cached in registers (whole block is one class); 1 atomic per block.
__global__ void __launch_bounds__(256) k_row(float* __restrict__ out) {
    __shared__ float wsum[8];
    int tid  = threadIdx.x;
    int lane = tid & 31;
    int w    = tid >> 5;
    int rbase = blockIdx.x * 128 + w * 16;

    const float4* XSv = (const float4*)(g_Xsum + (rbase >> 10) * NC) + lane * 2;
    float4 x0 = XSv[0];
    float4 x1 = XSv[1];

    float wacc = 0.0f;

    #pragma unroll 1
    for (int i0 = 0; i0 < 16; i0 += 4) {
        uint4 rv[4];
        #pragma unroll
        for (int j = 0; j < 4; ++j)
            rv[j] = *((const uint4*)(g_Rn + (size_t)(rbase + i0 + j) * NC) + lane);

        float dj[4];
        #pragma unroll
        for (int j = 0; j < 4; ++j) {
            const __nv_bfloat162* rp = (const __nv_bfloat162*)&rv[j];
            float d = 0.0f; float2 p;
            p = __bfloat1622float2(rp[0]); d = fmaf(p.x, x0.x, d); d = fmaf(p.y, x0.y, d);
            p = __bfloat1622float2(rp[1]); d = fmaf(p.x, x0.z, d); d = fmaf(p.y, x0.w, d);
            p = __bfloat1622float2(rp[2]); d = fmaf(p.x, x1.x, d); d = fmaf(p.y, x1.y, d);
            p = __bfloat1622float2(rp[3]); d = fmaf(p.x, x1.z, d); d = fmaf(p.y, x1.w, d);
            #pragma unroll
            for (int o = 16; o; o >>= 1) d += __shfl_xor_sync(0xffffffffu, d, o);
            dj[j] = d;
        }
        if (lane == 0) {
            #pragma unroll
            for (int j = 0; j < 4; ++j)
                wacc += 1024.0f * logf(g_rowsum[rbase + i0 + j]) - dj[j] * INV_T;
        }
    }

    if (lane == 0) wsum[w] = wacc;
    __syncthreads();

    if (tid == 0) {
        float bs = 0.0f;
        #pragma unroll
        for (int j = 0; j < 8; ++j) bs += wsum[j];
        atomicAdd(&g_acc, (double)bs);
        __threadfence();
        unsigned t = atomicAdd(&g_done, 1u);
        if (t == gridDim.x - 1) {
            out[0] = (float)(g_acc / (POS_COUNT + 1e-8));
        }
    }
}

extern "C" void kernel_launch(void* const* d_in, const int* in_sizes, int n_in,
                              void* d_out, int out_size) {
    const float* rgb = (const float*)d_in[0];
    const float* x   = (const float*)d_in[1];
    float* out = (float*)d_out;
    (void)in_sizes; (void)n_in; (void)out_size;

    const int GEMM_SMEM = 3 * 64 * 272;   // 52224 bytes
    cudaFuncSetAttribute(k_gemm, cudaFuncAttributeMaxDynamicSharedMemorySize, GEMM_SMEM);

    k_init<<<40, 256>>>();
    k_norm<<<512, 256>>>(rgb, x);
    k_gemm<<<512, 256, GEMM_SMEM>>>();
    k_row<<<64, 256>>>(out);
}

// round 8
// speedup vs baseline: 1.0712x; 1.0712x over previous
#include <cuda_runtime.h>
#include <cuda_bf16.h>
#include <math.h>
#include <stdint.h>

// Problem constants
#define NB 8
#define NC 256
#define NHW 1024
#define NROW 8192              // NB*NHW
#define INV_T 10.0f            // 1/TEMPERATURE
#define POS_COUNT 8388608.0    // 8192*1024

#define NRB 64                 // row blocks (128 rows each)
#define TILES_PER_RB 128       // 8192 cols / 64
#define GEMM_GRID 296          // 2 * 148 SMs (persistent)

// ---------------- device scratch (no allocation allowed) ----------------
__device__ __align__(256) __nv_bfloat16 g_Rn[NROW * NC];   // normalized rgb (bf16)
__device__ __align__(256) __nv_bfloat16 g_Xn[NROW * NC];   // normalized x   (bf16)
__device__ float  g_Xsum[8 * NC];           // per-batch column sums of normalized x
__device__ float  g_Rsum[8 * NC];           // per-batch column sums of normalized rgb
__device__ float  g_rowsum[NROW];           // sum_j exp(sim_ij)
__device__ int    g_rbctr[NRB];             // per-rowblock tile counters (work stealing)
__device__ double g_acc;                    // global loss accumulator
__device__ unsigned g_done;                 // k_final completion counter

__device__ __forceinline__ float ex2f(float x) {
    float r; asm("ex2.approx.f32 %0, %1;" : "=f"(r) : "f"(x)); return r;
}

// ---------------- init ---------------------------------------------------
__global__ void k_init() {
    int idx = blockIdx.x * blockDim.x + threadIdx.x;
    if (idx < NROW) g_rowsum[idx] = 0.0f;
    if (idx < 8 * NC) { g_Xsum[idx] = 0.0f; g_Rsum[idx] = 0.0f; }
    if (idx < NRB) g_rbctr[idx] = 0;
    if (idx == 0) { g_acc = 0.0; g_done = 0u; }
}

// ---------------- normalize (B,C,H,W) -> rows of 256, bf16 --------------
// grid 512: blocks [0,256) process rgb, [256,512) process x.
// Also accumulates per-batch sums of the normalized vectors (Rsum / Xsum).
__global__ void __launch_bounds__(256) k_norm(const float* __restrict__ rgb,
                                              const float* __restrict__ x) {
    __shared__ float s[32][257];
    __shared__ float ps[8][32];
    __shared__ float invs[32];

    int tid = threadIdx.x;
    int isX = blockIdx.x >> 8;
    int bix = blockIdx.x & 255;
    int b   = bix >> 5;
    int p0  = (bix & 31) << 5;
    int pl  = tid & 31;
    int cg  = tid >> 5;

    const float* in = isX ? x : rgb;
    const float* base = in + (size_t)b * NC * NHW + p0;
    #pragma unroll
    for (int co = 0; co < 32; ++co) {
        int c = co * 8 + cg;
        s[pl][c] = base[(size_t)c * NHW + pl];
    }
    __syncthreads();

    float part = 0.0f;
    #pragma unroll
    for (int k = 0; k < 32; ++k) {
        float v = s[pl][cg * 32 + k];
        part = fmaf(v, v, part);
    }
    ps[cg][pl] = part;
    __syncthreads();

    if (tid < 32) {
        float ss = 0.0f;
        #pragma unroll
        for (int j = 0; j < 8; ++j) ss += ps[j][tid];
        invs[tid] = 1.0f / fmaxf(sqrtf(ss), 1e-12f);
    }
    __syncthreads();

    __nv_bfloat16* out = isX ? g_Xn : g_Rn;
    float* sacc = isX ? g_Xsum : g_Rsum;

    float acc = 0.0f;
    #pragma unroll
    for (int rl = 0; rl < 32; ++rl) {
        float v = s[rl][tid] * invs[rl];
        out[(size_t)(b * NHW + p0 + rl) * NC + tid] = __float2bfloat16(v);
        acc += v;                      // all 32 pixels in this block share batch b
    }
    atomicAdd(&sacc[b * NC + tid], acc);
}

// ---------------- helpers for the GEMM ----------------------------------
__device__ __forceinline__ void mma16816(float c[4], const uint32_t a[4],
                                         uint32_t b0, uint32_t b1) {
    asm volatile(
        "mma.sync.aligned.m16n8k16.row.col.f32.bf16.bf16.f32 "
        "{%0,%1,%2,%3}, {%4,%5,%6,%7}, {%8,%9}, {%0,%1,%2,%3};"
        : "+f"(c[0]), "+f"(c[1]), "+f"(c[2]), "+f"(c[3])
        : "r"(a[0]), "r"(a[1]), "r"(a[2]), "r"(a[3]), "r"(b0), "r"(b1));
}

#define BUFW (64u * 132u * 4u)   // one 64x256 bf16 stage, padded stride 132 words

// issue 64x256 bf16 tile load (32KB) via cp.async, one commit group
__device__ __forceinline__ void issue_load64(uint32_t dst_base,
                                             const __nv_bfloat16* src_base,
                                             int w, int lane) {
    const char* src = (const char*)src_base + lane * 16;
    #pragma unroll
    for (int it = 0; it < 8; ++it) {
        int row = it * 8 + w;
        uint32_t dst = dst_base + (uint32_t)(row * 132 + lane * 4) * 4;
        asm volatile("cp.async.cg.shared.global [%0], [%1], 16;"
                     :: "r"(dst), "l"(src + (size_t)row * 512) : "memory");
    }
    asm volatile("cp.async.commit_group;" ::: "memory");
}

// tid0-only: sticky per-rowblock work stealing. Returns (rb<<8)|tile or -1.
__device__ __forceinline__ int next_job(int& rb, int& scan) {
    while (scan < NRB) {
        int t = atomicAdd(&g_rbctr[rb], 1);
        if (t < TILES_PER_RB) { scan = 0; return (rb << 8) | t; }
        rb = (rb + 1) & (NRB - 1); ++scan;
    }
    return -1;
}

// ---------------- fused GEMM + exp row-sum (persistent) ------------------
// 296 persistent CTAs; jobs = (rowblock, 64-col tile); A register-resident
// per rowblock; triple-buffered cp.async prefetch, depth 2, 1 sync/tile.
__global__ void __launch_bounds__(256, 2) k_gemm() {
    extern __shared__ uint32_t Xs[];   // 3 stages of 64*132 words
    __shared__ int s_job[2];

    int tid  = threadIdx.x;
    int w    = tid >> 5;
    int lane = tid & 31;
    int g    = lane >> 2;
    int tig  = lane & 3;

    // tid0 scheduler state
    int my_rb = blockIdx.x & (NRB - 1);
    int scan  = 0;

    // ldmatrix per-lane offset (q=0, kc=0), in words
    int mi = lane >> 3, rr = lane & 7;
    int ldsm_off = (((mi >> 1) * 8) + rr) * 132 + (mi & 1) * 4;

    uint32_t sbase = (uint32_t)__cvta_generic_to_shared(Xs);
    const float S = 14.426950408889634f;   // log2(e)/0.1

    // ---- prologue: fetch two jobs, start their loads ----
    if (tid == 0) s_job[0] = next_job(my_rb, scan);
    __syncthreads();
    int j0 = s_job[0];
    if (j0 < 0) return;
    issue_load64(sbase, g_Xn + (size_t)(j0 & 255) * 64 * NC, w, lane);

    if (tid == 0) s_job[1] = next_job(my_rb, scan);
    __syncthreads();
    int j1 = s_job[1];
    if (j1 >= 0)
        issue_load64(sbase + BUFW, g_Xn + (size_t)(j1 & 255) * 64 * NC, w, lane);

    uint32_t a[16][4];        // A fragments, K=256, for current rowblock
    int cur_rb = -1;
    float rs0 = 0.0f, rs1 = 0.0f;
    int st = 0;

    while (j0 >= 0) {
        if (tid == 0) s_job[st & 1] = next_job(my_rb, scan);   // fetch j2
        if (j1 >= 0) { asm volatile("cp.async.wait_group 1;" ::: "memory"); }
        else         { asm volatile("cp.async.wait_group 0;" ::: "memory"); }
        __syncthreads();   // j0 data visible; prev compute done; s_job visible

        int j2 = s_job[st & 1];
        if (j2 >= 0) {
            uint32_t dst = sbase + (uint32_t)((st + 2) % 3) * BUFW;
            issue_load64(dst, g_Xn + (size_t)(j2 & 255) * 64 * NC, w, lane);
        }

        // A fragments / rowsum flush on rowblock change
        int rbn = j0 >> 8;
        if (rbn != cur_rb) {
            if (cur_rb >= 0) {
                float r0 = rs0, r1 = rs1;
                r0 += __shfl_xor_sync(0xffffffffu, r0, 1);
                r0 += __shfl_xor_sync(0xffffffffu, r0, 2);
                r1 += __shfl_xor_sync(0xffffffffu, r1, 1);
                r1 += __shfl_xor_sync(0xffffffffu, r1, 2);
                if (tig == 0) {
                    int rg = cur_rb * 128 + w * 16 + g;
                    atomicAdd(&g_rowsum[rg], r0);
                    atomicAdd(&g_rowsum[rg + 8], r1);
                }
                rs0 = 0.0f; rs1 = 0.0f;
            }
            const __nv_bfloat16* Ra = g_Rn + (size_t)(rbn * 128 + w * 16 + g) * NC;
            const __nv_bfloat16* Rb = Ra + 8 * NC;
            #pragma unroll
            for (int kc = 0; kc < 16; ++kc) {
                a[kc][0] = *(const uint32_t*)(Ra + kc * 16 + 2 * tig);
                a[kc][1] = *(const uint32_t*)(Rb + kc * 16 + 2 * tig);
                a[kc][2] = *(const uint32_t*)(Ra + kc * 16 + 8 + 2 * tig);
                a[kc][3] = *(const uint32_t*)(Rb + kc * 16 + 8 + 2 * tig);
            }
            cur_rb = rbn;
        }

        // ---- compute one 64-col tile ----
        uint32_t tile_base = sbase + (uint32_t)(st % 3) * BUFW + (uint32_t)ldsm_off * 4;
        #pragma unroll
        for (int half = 0; half < 2; ++half) {
            float c[4][4];
            #pragma unroll
            for (int n8 = 0; n8 < 4; ++n8) {
                c[n8][0] = 0.f; c[n8][1] = 0.f; c[n8][2] = 0.f; c[n8][3] = 0.f;
            }
            uint32_t ld_base = tile_base + (uint32_t)(half * 2 * 2112) * 4;
            #pragma unroll
            for (int kc = 0; kc < 16; ++kc) {
                #pragma unroll
                for (int q = 0; q < 2; ++q) {
                    uint32_t b0, b1, b2, b3;
                    uint32_t ad = ld_base + (uint32_t)(q * 2112 + kc * 8) * 4;
                    asm volatile(
                        "ldmatrix.sync.aligned.m8n8.x4.shared.b16 {%0,%1,%2,%3}, [%4];"
                        : "=r"(b0), "=r"(b1), "=r"(b2), "=r"(b3) : "r"(ad));
                    mma16816(c[2 * q],     a[kc], b0, b1);
                    mma16816(c[2 * q + 1], a[kc], b2, b3);
                }
            }
            #pragma unroll
            for (int n8 = 0; n8 < 4; ++n8) {
                rs0 += ex2f(c[n8][0] * S) + ex2f(c[n8][1] * S);
                rs1 += ex2f(c[n8][2] * S) + ex2f(c[n8][3] * S);
            }
        }

        j0 = j1; j1 = j2; ++st;
    }

    // final flush
    if (cur_rb >= 0) {
        rs0 += __shfl_xor_sync(0xffffffffu, rs0, 1);
        rs0 += __shfl_xor_sync(0xffffffffu, rs0, 2);
        rs1 += __shfl_xor_sync(0xffffffffu, rs1, 1);
        rs1 += __shfl_xor_sync(0xffffffffu, rs1, 2);
        if (tig == 0) {
            int rg = cur_rb * 128 + w * 16 + g;
            atomicAdd(&g_rowsum[rg], rs0);
            atomicAdd(&g_rowsum[rg + 8], rs1);
        }
    }
}

// ---------------- final: sum 1024*ln(rowsum) - INV_T*dot(Rsum,Xsum) -----
// grid 32 x 256: one row per thread; block 0 also computes the positive dot.
__global__ void __launch_bounds__(256) k_final(float* __restrict__ out) {
    __shared__ float wsum[8];
    __shared__ float psum[8];
    int tid  = threadIdx.x;
    int lane = tid & 31;
    int w    = tid >> 5;
    int row  = blockIdx.x * 256 + tid;

    float v = 1024.0f * __logf(g_rowsum[row]);
    #pragma unroll
    for (int o = 16; o; o >>= 1) v += __shfl_xor_sync(0xffffffffu, v, o);
    if (lane == 0) wsum[w] = v;

    float pd = 0.0f;
    if (blockIdx.x == 0) {
        #pragma unroll
        for (int b = 0; b < 8; ++b)
            pd = fmaf(g_Rsum[b * NC + tid], g_Xsum[b * NC + tid], pd);
        #pragma unroll
        for (int o = 16; o; o >>= 1) pd += __shfl_xor_sync(0xffffffffu, pd, o);
        if (lane == 0) psum[w] = pd;
    }
    __syncthreads();

    if (tid == 0) {
        float bs = 0.0f;
        #pragma unroll
        for (int j = 0; j < 8; ++j) bs += wsum[j];
        if (blockIdx.x == 0) {
            float pp = 0.0f;
            #pragma unroll
            for (int j = 0; j < 8; ++j) pp += psum[j];
            bs -= pp * INV_T;
        }
        atomicAdd(&g_acc, (double)bs);
        __threadfence();
        unsigned t = atomicAdd(&g_done, 1u);
        if (t == gridDim.x - 1) {
            out[0] = (float)(g_acc / (POS_COUNT + 1e-8));
        }
    }
}

extern "C" void kernel_launch(void* const* d_in, const int* in_sizes, int n_in,
                              void* d_out, int out_size) {
    const float* rgb = (const float*)d_in[0];
    const float* x   = (const float*)d_in[1];
    float* out = (float*)d_out;
    (void)in_sizes; (void)n_in; (void)out_size;

    const int GEMM_SMEM = 3 * 64 * 132 * 4;   // 101376 bytes
    cudaFuncSetAttribute(k_gemm, cudaFuncAttributeMaxDynamicSharedMemorySize, GEMM_SMEM);

    k_init<<<40, 256>>>();
    k_norm<<<512, 256>>>(rgb, x);
    k_gemm<<<GEMM_GRID, 256, GEMM_SMEM>>>();
    k_final<<<32, 256>>>(out);
}

// round 9
// speedup vs baseline: 1.2709x; 1.1864x over previous
#include <cuda_runtime.h>
#include <cuda_bf16.h>
#include <math.h>
#include <stdint.h>

// Problem constants
#define NB 8
#define NC 256
#define NHW 1024
#define NROW 8192              // NB*NHW
#define INV_T 10.0f            // 1/TEMPERATURE
#define POS_COUNT 8388608.0    // 8192*1024

// ---------------- device scratch (no allocation allowed) ----------------
__device__ __align__(256) __nv_bfloat16 g_Rn[NROW * NC];   // normalized rgb (bf16)
__device__ __align__(256) __nv_bfloat16 g_Xn[NROW * NC];   // normalized x   (bf16)
__device__ float  g_Xsum[8 * NC];           // per-batch column sums of normalized x
__device__ float  g_Rsum[8 * NC];           // per-batch column sums of normalized rgb
__device__ float  g_rowpart[8][NROW];       // per-colslice exp-sum partials (no atomics)
__device__ double g_acc;                    // global loss accumulator
__device__ unsigned g_done;                 // k_final completion counter

__device__ __forceinline__ float ex2f(float x) {
    float r; asm("ex2.approx.f32 %0, %1;" : "=f"(r) : "f"(x)); return r;
}

// ---------------- init: 1 block, tiny ------------------------------------
__global__ void k_init() {
    int tid = threadIdx.x;
    #pragma unroll
    for (int i = 0; i < 8; ++i) {
        g_Xsum[tid + i * 256] = 0.0f;
        g_Rsum[tid + i * 256] = 0.0f;
    }
    if (tid == 0) { g_acc = 0.0; g_done = 0u; }
}

// ---------------- normalize (B,C,H,W) -> rows of 256, bf16 --------------
// grid 512: blocks [0,256) process rgb, [256,512) process x.
// Also accumulates per-batch sums of the normalized vectors (Rsum / Xsum).
__global__ void __launch_bounds__(256) k_norm(const float* __restrict__ rgb,
                                              const float* __restrict__ x) {
    __shared__ float s[32][257];
    __shared__ float ps[8][32];
    __shared__ float invs[32];

    int tid = threadIdx.x;
    int isX = blockIdx.x >> 8;
    int bix = blockIdx.x & 255;
    int b   = bix >> 5;
    int p0  = (bix & 31) << 5;
    int pl  = tid & 31;
    int cg  = tid >> 5;

    const float* in = isX ? x : rgb;
    const float* base = in + (size_t)b * NC * NHW + p0;
    #pragma unroll
    for (int co = 0; co < 32; ++co) {
        int c = co * 8 + cg;
        s[pl][c] = base[(size_t)c * NHW + pl];
    }
    __syncthreads();

    float part = 0.0f;
    #pragma unroll
    for (int k = 0; k < 32; ++k) {
        float v = s[pl][cg * 32 + k];
        part = fmaf(v, v, part);
    }
    ps[cg][pl] = part;
    __syncthreads();

    if (tid < 32) {
        float ss = 0.0f;
        #pragma unroll
        for (int j = 0; j < 8; ++j) ss += ps[j][tid];
        invs[tid] = 1.0f / fmaxf(sqrtf(ss), 1e-12f);
    }
    __syncthreads();

    __nv_bfloat16* out = isX ? g_Xn : g_Rn;
    float* sacc = isX ? g_Xsum : g_Rsum;

    float acc = 0.0f;
    #pragma unroll
    for (int rl = 0; rl < 32; ++rl) {
        float v = s[rl][tid] * invs[rl];
        out[(size_t)(b * NHW + p0 + rl) * NC + tid] = __float2bfloat16(v);
        acc += v;                      // all 32 pixels in this block share batch b
    }
    atomicAdd(&sacc[b * NC + tid], acc);
}

// ---------------- helpers for the GEMM ----------------------------------
__device__ __forceinline__ void mma16816(float c[4], const uint32_t a[4],
                                         uint32_t b0, uint32_t b1) {
    asm volatile(
        "mma.sync.aligned.m16n8k16.row.col.f32.bf16.bf16.f32 "
        "{%0,%1,%2,%3}, {%4,%5,%6,%7}, {%8,%9}, {%0,%1,%2,%3};"
        : "+f"(c[0]), "+f"(c[1]), "+f"(c[2]), "+f"(c[3])
        : "r"(a[0]), "r"(a[1]), "r"(a[2]), "r"(a[3]), "r"(b0), "r"(b1));
}
__device__ __forceinline__ void ldsm4(uint32_t b[4], uint32_t addr) {
    asm volatile("ldmatrix.sync.aligned.m8n8.x4.shared.b16 {%0,%1,%2,%3}, [%4];"
                 : "=r"(b[0]), "=r"(b[1]), "=r"(b[2]), "=r"(b[3]) : "r"(addr));
}

#define BUFW (64u * 132u * 4u)   // one 64x256 bf16 stage, padded stride 132 words

// issue 64x256 bf16 tile load (32KB) via cp.async, one commit group
__device__ __forceinline__ void issue_load64(uint32_t dst_base,
                                             const __nv_bfloat16* src_base,
                                             int w, int lane) {
    const char* src = (const char*)src_base + lane * 16;
    #pragma unroll
    for (int it = 0; it < 8; ++it) {
        int row = it * 8 + w;
        uint32_t dst = dst_base + (uint32_t)(row * 132 + lane * 4) * 4;
        asm volatile("cp.async.cg.shared.global [%0], [%1], 16;"
                     :: "r"(dst), "l"(src + (size_t)row * 512) : "memory");
    }
    asm volatile("cp.async.commit_group;" ::: "memory");
}

// ---------------- fused GEMM + exp row-sum ------------------------------
// 512 blocks: 64 row-blocks (128 rows) x 8 column slices (1024 cols).
// Per CTA: 16 B-tiles of 64 cols, 3-stage cp.async pipeline, 1 sync/tile.
// 8 warps; warp owns 16 rows; A register-resident for full K=256.
// Explicit LDSM->HMMA software pipeline (B fragments one step ahead).
__global__ void __launch_bounds__(256, 2) k_gemm() {
    extern __shared__ uint32_t Xs[];   // 3 stages of 64*132 words

    int tid  = threadIdx.x;
    int w    = tid >> 5;
    int lane = tid & 31;
    int g    = lane >> 2;
    int tig  = lane & 3;

    int rowBlk = blockIdx.x & 63;
    int cslice = blockIdx.x >> 6;          // 0..7
    int r0     = rowBlk * 128;
    int cstart = cslice * 1024;

    int rg = r0 + w * 16 + g;
    const __nv_bfloat16* Ra = g_Rn + (size_t)rg * NC;
    const __nv_bfloat16* Rb = g_Rn + (size_t)(rg + 8) * NC;

    // A fragments for full K=256
    uint32_t a[16][4];
    #pragma unroll
    for (int kc = 0; kc < 16; ++kc) {
        a[kc][0] = *(const uint32_t*)(Ra + kc * 16 + 2 * tig);
        a[kc][1] = *(const uint32_t*)(Rb + kc * 16 + 2 * tig);
        a[kc][2] = *(const uint32_t*)(Ra + kc * 16 + 8 + 2 * tig);
        a[kc][3] = *(const uint32_t*)(Rb + kc * 16 + 8 + 2 * tig);
    }

    // ldmatrix per-lane offset (q=0, kc=0), in words
    int mi = lane >> 3, rr = lane & 7;
    int ldsm_off = (((mi >> 1) * 8) + rr) * 132 + (mi & 1) * 4;

    uint32_t sbase = (uint32_t)__cvta_generic_to_shared(Xs);
    const float S = 14.426950408889634f;   // log2(e)/0.1

    float rs0 = 0.0f, rs1 = 0.0f;

    const __nv_bfloat16* xb = g_Xn + (size_t)cstart * NC;
    issue_load64(sbase,        xb,           w, lane);
    issue_load64(sbase + BUFW, xb + 64 * NC, w, lane);

    #pragma unroll 1
    for (int nt = 0; nt < 16; ++nt) {
        if (nt < 15) {
            asm volatile("cp.async.wait_group 1;" ::: "memory");
        } else {
            asm volatile("cp.async.wait_group 0;" ::: "memory");
        }
        __syncthreads();   // all warps done with iter nt-1; buf (nt+2)%3 free; buf nt%3 visible
        if (nt + 2 < 16)
            issue_load64(sbase + (uint32_t)((nt + 2) % 3) * BUFW,
                         xb + (size_t)(nt + 2) * 64 * NC, w, lane);

        uint32_t tile_base = sbase + (uint32_t)(nt % 3) * BUFW + (uint32_t)ldsm_off * 4;

        #pragma unroll
        for (int half = 0; half < 2; ++half) {
            float c[4][4];
            #pragma unroll
            for (int n8 = 0; n8 < 4; ++n8) {
                c[n8][0] = 0.f; c[n8][1] = 0.f; c[n8][2] = 0.f; c[n8][3] = 0.f;
            }
            uint32_t ld_base = tile_base + (uint32_t)(half * 2 * 2112) * 4;

            // software pipeline: b fragments loaded one (kc,q) step ahead
            uint32_t bb[2][4];
            ldsm4(bb[0], ld_base);                 // (kc=0, q=0)
            #pragma unroll
            for (int i = 0; i < 32; ++i) {
                int kc = i >> 1, q = i & 1;
                int ni = i + 1;
                if (ni < 32) {
                    uint32_t nad = ld_base + (uint32_t)((ni & 1) * 2112 + (ni >> 1) * 8) * 4;
                    ldsm4(bb[ni & 1], nad);
                }
                uint32_t* bq = bb[q];
                mma16816(c[2 * q],     a[kc], bq[0], bq[1]);
                mma16816(c[2 * q + 1], a[kc], bq[2], bq[3]);
            }

            #pragma unroll
            for (int n8 = 0; n8 < 4; ++n8) {
                rs0 += ex2f(c[n8][0] * S) + ex2f(c[n8][1] * S);
                rs1 += ex2f(c[n8][2] * S) + ex2f(c[n8][3] * S);
            }
        }
    }

    rs0 += __shfl_xor_sync(0xffffffffu, rs0, 1);
    rs0 += __shfl_xor_sync(0xffffffffu, rs0, 2);
    rs1 += __shfl_xor_sync(0xffffffffu, rs1, 1);
    rs1 += __shfl_xor_sync(0xffffffffu, rs1, 2);
    if (tig == 0) {
        g_rowpart[cslice][rg]     = rs0;   // plain stores, slab per colslice
        g_rowpart[cslice][rg + 8] = rs1;
    }
}

// ---------------- final: sum 1024*ln(rowsum) - INV_T*dot(Rsum,Xsum) -----
// grid 8 x 256: thread handles 4 rows; block 0 also computes the positive dot.
__global__ void __launch_bounds__(256) k_final(float* __restrict__ out) {
    __shared__ float wsum[8];
    __shared__ float psum[8];
    int tid  = threadIdx.x;
    int lane = tid & 31;
    int w    = tid >> 5;

    float v = 0.0f;
    #pragma unroll
    for (int j = 0; j < 4; ++j) {
        int row = blockIdx.x * 1024 + j * 256 + tid;
        float s = 0.0f;
        #pragma unroll
        for (int cs = 0; cs < 8; ++cs) s += g_rowpart[cs][row];
        v += __logf(s);
    }
    v *= 1024.0f;
    #pragma unroll
    for (int o = 16; o; o >>= 1) v += __shfl_xor_sync(0xffffffffu, v, o);
    if (lane == 0) wsum[w] = v;

    if (blockIdx.x == 0) {
        float pd = 0.0f;
        #pragma unroll
        for (int b = 0; b < 8; ++b)
            pd = fmaf(g_Rsum[b * NC + tid], g_Xsum[b * NC + tid], pd);
        #pragma unroll
        for (int o = 16; o; o >>= 1) pd += __shfl_xor_sync(0xffffffffu, pd, o);
        if (lane == 0) psum[w] = pd;
    }
    __syncthreads();

    if (tid == 0) {
        float bs = 0.0f;
        #pragma unroll
        for (int j = 0; j < 8; ++j) bs += wsum[j];
        if (blockIdx.x == 0) {
            float pp = 0.0f;
            #pragma unroll
            for (int j = 0; j < 8; ++j) pp += psum[j];
            bs -= pp * INV_T;
        }
        atomicAdd(&g_acc, (double)bs);
        __threadfence();
        unsigned t = atomicAdd(&g_done, 1u);
        if (t == gridDim.x - 1) {
            out[0] = (float)(g_acc / (POS_COUNT + 1e-8));
        }
    }
}

extern "C" void kernel_launch(void* const* d_in, const int* in_sizes, int n_in,
                              void* d_out, int out_size) {
    const float* rgb = (const float*)d_in[0];
    const float* x   = (const float*)d_in[1];
    float* out = (float*)d_out;
    (void)in_sizes; (void)n_in; (void)out_size;

    const int GEMM_SMEM = 3 * 64 * 132 * 4;   // 101376 bytes
    cudaFuncSetAttribute(k_gemm, cudaFuncAttributeMaxDynamicSharedMemorySize, GEMM_SMEM);

    k_init<<<1, 256>>>();
    k_norm<<<512, 256>>>(rgb, x);
    k_gemm<<<512, 256, GEMM_SMEM>>>();
    k_final<<<8, 256>>>(out);
}

// round 10
// speedup vs baseline: 1.3874x; 1.0917x over previous
#include <cuda_runtime.h>
#include <cuda_bf16.h>
#include <math.h>
#include <stdint.h>

// Problem constants
#define NB 8
#define NC 256
#define NHW 1024
#define NROW 8192              // NB*NHW
#define INV_T 10.0f            // 1/TEMPERATURE
#define POS_COUNT 8388608.0    // 8192*1024

#define GEMM_GRID 296          // 2 CTAs/SM * 148 SMs, single balanced wave
#define NJOBS 8192             // 64 rowblocks * 128 col-tiles (64 cols each)

// ---------------- device scratch (no allocation allowed) ----------------
__device__ __align__(256) __nv_bfloat16 g_Rn[NROW * NC];   // normalized rgb (bf16)
__device__ __align__(256) __nv_bfloat16 g_Xn[NROW * NC];   // normalized x   (bf16)
__device__ float  g_Xsum[8 * NC];           // per-batch column sums of normalized x
__device__ float  g_Rsum[8 * NC];           // per-batch column sums of normalized rgb
__device__ float  g_rowsum[NROW];           // sum_j exp(sim_ij)
__device__ double g_acc;                    // global loss accumulator
__device__ unsigned g_done;                 // k_final completion counter

__device__ __forceinline__ float ex2f(float x) {
    float r; asm("ex2.approx.f32 %0, %1;" : "=f"(r) : "f"(x)); return r;
}

// ---------------- init ----------------------------------------------------
__global__ void k_init() {
    int idx = blockIdx.x * 256 + threadIdx.x;
    g_rowsum[idx] = 0.0f;
    if (idx < 8 * NC) { g_Xsum[idx] = 0.0f; g_Rsum[idx] = 0.0f; }
    if (idx == 0) { g_acc = 0.0; g_done = 0u; }
}

// ---------------- normalize (B,C,H,W) -> rows of 256, bf16 --------------
// grid 512: blocks [0,256) process rgb, [256,512) process x.
// Also accumulates per-batch sums of the normalized vectors (Rsum / Xsum).
__global__ void __launch_bounds__(256) k_norm(const float* __restrict__ rgb,
                                              const float* __restrict__ x) {
    __shared__ float s[32][257];
    __shared__ float ps[8][32];
    __shared__ float invs[32];

    int tid = threadIdx.x;
    int isX = blockIdx.x >> 8;
    int bix = blockIdx.x & 255;
    int b   = bix >> 5;
    int p0  = (bix & 31) << 5;
    int pl  = tid & 31;
    int cg  = tid >> 5;

    const float* in = isX ? x : rgb;
    const float* base = in + (size_t)b * NC * NHW + p0;
    #pragma unroll
    for (int co = 0; co < 32; ++co) {
        int c = co * 8 + cg;
        s[pl][c] = base[(size_t)c * NHW + pl];
    }
    __syncthreads();

    float part = 0.0f;
    #pragma unroll
    for (int k = 0; k < 32; ++k) {
        float v = s[pl][cg * 32 + k];
        part = fmaf(v, v, part);
    }
    ps[cg][pl] = part;
    __syncthreads();

    if (tid < 32) {
        float ss = 0.0f;
        #pragma unroll
        for (int j = 0; j < 8; ++j) ss += ps[j][tid];
        invs[tid] = 1.0f / fmaxf(sqrtf(ss), 1e-12f);
    }
    __syncthreads();

    __nv_bfloat16* out = isX ? g_Xn : g_Rn;
    float* sacc = isX ? g_Xsum : g_Rsum;

    float acc = 0.0f;
    #pragma unroll
    for (int rl = 0; rl < 32; ++rl) {
        float v = s[rl][tid] * invs[rl];
        out[(size_t)(b * NHW + p0 + rl) * NC + tid] = __float2bfloat16(v);
        acc += v;                      // all 32 pixels in this block share batch b
    }
    atomicAdd(&sacc[b * NC + tid], acc);
}

// ---------------- helpers for the GEMM ----------------------------------
__device__ __forceinline__ void mma16816(float c[4], const uint32_t a[4],
                                         uint32_t b0, uint32_t b1) {
    asm volatile(
        "mma.sync.aligned.m16n8k16.row.col.f32.bf16.bf16.f32 "
        "{%0,%1,%2,%3}, {%4,%5,%6,%7}, {%8,%9}, {%0,%1,%2,%3};"
        : "+f"(c[0]), "+f"(c[1]), "+f"(c[2]), "+f"(c[3])
        : "r"(a[0]), "r"(a[1]), "r"(a[2]), "r"(a[3]), "r"(b0), "r"(b1));
}
__device__ __forceinline__ void ldsm4(uint32_t b[4], uint32_t addr) {
    asm volatile("ldmatrix.sync.aligned.m8n8.x4.shared.b16 {%0,%1,%2,%3}, [%4];"
                 : "=r"(b[0]), "=r"(b[1]), "=r"(b[2]), "=r"(b[3]) : "r"(addr));
}

#define BUFW (64u * 132u * 4u)   // one 64x256 bf16 stage, padded stride 132 words

// issue 64x256 bf16 tile load (32KB) via cp.async, one commit group
__device__ __forceinline__ void issue_job(uint32_t dst_base, int job, int w, int lane) {
    const __nv_bfloat16* src_base = g_Xn + (size_t)(job & 127) * 64 * NC;
    const char* src = (const char*)src_base + lane * 16;
    #pragma unroll
    for (int it = 0; it < 8; ++it) {
        int row = it * 8 + w;
        uint32_t dst = dst_base + (uint32_t)(row * 132 + lane * 4) * 4;
        asm volatile("cp.async.cg.shared.global [%0], [%1], 16;"
                     :: "r"(dst), "l"(src + (size_t)row * 512) : "memory");
    }
    asm volatile("cp.async.commit_group;" ::: "memory");
}

// ---------------- fused GEMM + exp row-sum (static persistent) ----------
// 296 CTAs, each a contiguous range of the 8192 (rowblock, col-tile) jobs.
// job j: rowblock = j>>7 (128 rows), col tile = (j&127)*64.
// 8 warps; warp owns 16 rows; A register-resident per rowblock.
// 3-stage cp.async pipeline, 1 sync/job; LDSM->HMMA software pipeline.
__global__ void __launch_bounds__(256, 2) k_gemm() {
    extern __shared__ uint32_t Xs[];   // 3 stages of 64*132 words

    int tid  = threadIdx.x;
    int w    = tid >> 5;
    int lane = tid & 31;
    int g    = lane >> 2;
    int tig  = lane & 3;

    int k0 = (int)(((long long)blockIdx.x * NJOBS) / GEMM_GRID);
    int k1 = (int)(((long long)(blockIdx.x + 1) * NJOBS) / GEMM_GRID);

    // ldmatrix per-lane offset (q=0, kc=0), in words
    int mi = lane >> 3, rr = lane & 7;
    int ldsm_off = (((mi >> 1) * 8) + rr) * 132 + (mi & 1) * 4;

    uint32_t sbase = (uint32_t)__cvta_generic_to_shared(Xs);
    const float S = 14.426950408889634f;   // log2(e)/0.1

    issue_job(sbase, k0, w, lane);
    if (k0 + 1 < k1) issue_job(sbase + BUFW, k0 + 1, w, lane);

    uint32_t a[16][4];        // A fragments, K=256, for current rowblock
    int cur_rb = -1;
    float rs0 = 0.0f, rs1 = 0.0f;

    #pragma unroll 1
    for (int j = k0; j < k1; ++j) {
        int st = j - k0;
        if (j + 1 < k1) { asm volatile("cp.async.wait_group 1;" ::: "memory"); }
        else            { asm volatile("cp.async.wait_group 0;" ::: "memory"); }
        __syncthreads();   // all warps done with job j-1; stage (st+2)%3 free; stage st%3 visible
        if (j + 2 < k1)
            issue_job(sbase + (uint32_t)((st + 2) % 3) * BUFW, j + 2, w, lane);

        // rowblock change: flush rowsums, reload A fragments
        int rbn = j >> 7;
        if (rbn != cur_rb) {
            if (cur_rb >= 0) {
                float r0 = rs0, r1 = rs1;
                r0 += __shfl_xor_sync(0xffffffffu, r0, 1);
                r0 += __shfl_xor_sync(0xffffffffu, r0, 2);
                r1 += __shfl_xor_sync(0xffffffffu, r1, 1);
                r1 += __shfl_xor_sync(0xffffffffu, r1, 2);
                if (tig == 0) {
                    int rg = cur_rb * 128 + w * 16 + g;
                    atomicAdd(&g_rowsum[rg], r0);
                    atomicAdd(&g_rowsum[rg + 8], r1);
                }
                rs0 = 0.0f; rs1 = 0.0f;
            }
            const __nv_bfloat16* Ra = g_Rn + (size_t)(rbn * 128 + w * 16 + g) * NC;
            const __nv_bfloat16* Rb = Ra + 8 * NC;
            #pragma unroll
            for (int kc = 0; kc < 16; ++kc) {
                a[kc][0] = *(const uint32_t*)(Ra + kc * 16 + 2 * tig);
                a[kc][1] = *(const uint32_t*)(Rb + kc * 16 + 2 * tig);
                a[kc][2] = *(const uint32_t*)(Ra + kc * 16 + 8 + 2 * tig);
                a[kc][3] = *(const uint32_t*)(Rb + kc * 16 + 8 + 2 * tig);
            }
            cur_rb = rbn;
        }

        uint32_t tile_base = sbase + (uint32_t)(st % 3) * BUFW + (uint32_t)ldsm_off * 4;

        #pragma unroll
        for (int half = 0; half < 2; ++half) {
            float c[4][4];
            #pragma unroll
            for (int n8 = 0; n8 < 4; ++n8) {
                c[n8][0] = 0.f; c[n8][1] = 0.f; c[n8][2] = 0.f; c[n8][3] = 0.f;
            }
            uint32_t ld_base = tile_base + (uint32_t)(half * 2 * 2112) * 4;

            // software pipeline: b fragments loaded one (kc,q) step ahead
            uint32_t bb[2][4];
            ldsm4(bb[0], ld_base);                 // (kc=0, q=0)
            #pragma unroll
            for (int i = 0; i < 32; ++i) {
                int kc = i >> 1, q = i & 1;
                int ni = i + 1;
                if (ni < 32) {
                    uint32_t nad = ld_base + (uint32_t)((ni & 1) * 2112 + (ni >> 1) * 8) * 4;
                    ldsm4(bb[ni & 1], nad);
                }
                uint32_t* bq = bb[q];
                mma16816(c[2 * q],     a[kc], bq[0], bq[1]);
                mma16816(c[2 * q + 1], a[kc], bq[2], bq[3]);
            }

            #pragma unroll
            for (int n8 = 0; n8 < 4; ++n8) {
                rs0 += ex2f(c[n8][0] * S) + ex2f(c[n8][1] * S);
                rs1 += ex2f(c[n8][2] * S) + ex2f(c[n8][3] * S);
            }
        }
    }

    // final flush
    if (cur_rb >= 0) {
        rs0 += __shfl_xor_sync(0xffffffffu, rs0, 1);
        rs0 += __shfl_xor_sync(0xffffffffu, rs0, 2);
        rs1 += __shfl_xor_sync(0xffffffffu, rs1, 1);
        rs1 += __shfl_xor_sync(0xffffffffu, rs1, 2);
        if (tig == 0) {
            int rg = cur_rb * 128 + w * 16 + g;
            atomicAdd(&g_rowsum[rg], rs0);
            atomicAdd(&g_rowsum[rg + 8], rs1);
        }
    }
}

// ---------------- final: sum 1024*ln(rowsum) - INV_T*dot(Rsum,Xsum) -----
// grid 32 x 256: one row per thread; block 0 also computes the positive dot.
__global__ void __launch_bounds__(256) k_final(float* __restrict__ out) {
    __shared__ float wsum[8];
    __shared__ float psum[8];
    int tid  = threadIdx.x;
    int lane = tid & 31;
    int w    = tid >> 5;
    int row  = blockIdx.x * 256 + tid;

    float v = 1024.0f * __logf(g_rowsum[row]);
    #pragma unroll
    for (int o = 16; o; o >>= 1) v += __shfl_xor_sync(0xffffffffu, v, o);
    if (lane == 0) wsum[w] = v;

    if (blockIdx.x == 0) {
        float pd = 0.0f;
        #pragma unroll
        for (int b = 0; b < 8; ++b)
            pd = fmaf(g_Rsum[b * NC + tid], g_Xsum[b * NC + tid], pd);
        #pragma unroll
        for (int o = 16; o; o >>= 1) pd += __shfl_xor_sync(0xffffffffu, pd, o);
        if (lane == 0) psum[w] = pd;
    }
    __syncthreads();

    if (tid == 0) {
        float bs = 0.0f;
        #pragma unroll
        for (int j = 0; j < 8; ++j) bs += wsum[j];
        if (blockIdx.x == 0) {
            float pp = 0.0f;
            #pragma unroll
            for (int j = 0; j < 8; ++j) pp += psum[j];
            bs -= pp * INV_T;
        }
        atomicAdd(&g_acc, (double)bs);
        __threadfence();
        unsigned t = atomicAdd(&g_done, 1u);
        if (t == gridDim.x - 1) {
            out[0] = (float)(g_acc / (POS_COUNT + 1e-8));
        }
    }
}

extern "C" void kernel_launch(void* const* d_in, const int* in_sizes, int n_in,
                              void* d_out, int out_size) {
    const float* rgb = (const float*)d_in[0];
    const float* x   = (const float*)d_in[1];
    float* out = (float*)d_out;
    (void)in_sizes; (void)n_in; (void)out_size;

    const int GEMM_SMEM = 3 * 64 * 132 * 4;   // 101376 bytes
    cudaFuncSetAttribute(k_gemm, cudaFuncAttributeMaxDynamicSharedMemorySize, GEMM_SMEM);

    k_init<<<32, 256>>>();
    k_norm<<<512, 256>>>(rgb, x);
    k_gemm<<<GEMM_GRID, 256, GEMM_SMEM>>>();
    k_final<<<32, 256>>>(out);
}